// round 8
// baseline (speedup 1.0000x reference)
#include <cuda_runtime.h>
#include <math.h>

// Problem constants
#define BATCH   8
#define HGT     32
#define WID     32
#define CDIM    768
#define NHEAD   12
#define HDIM    64
#define NTOK    8
#define NSEQ    1032            // H*W + NT
#define BNH     96              // BATCH*NHEAD
#define MTOT    8256            // BATCH*NSEQ
#define QKSCALE 0.125f          // hd^-0.5

// Scratch (device globals; no allocation allowed)
__device__ float g_q [BNH * NSEQ * HDIM];         // [bh][n][d]
__device__ float g_kt[BNH * HDIM * NSEQ];         // [bh][d][n]  (transposed!)
__device__ float g_v [BNH * NSEQ * HDIM];         // [bh][n][d]
__device__ float g_o [BATCH * NSEQ * CDIM];       // [b][n][head*64+d]  (pre-proj)
__device__ float g_relh[BNH * 32 * 32 * 32];      // [bh][qh][qw][kh]
__device__ float g_relw[BNH * 32 * 32 * 32];      // [bh][qh][qw][kw]

// ---------------------------------------------------------------------------
// Kernel 1: QKV GEMM.  C[m][j] = xs[m][:] @ qkv_w[:, j] + qkv_b[j]
// 128x128 tile, BK=16, 256 threads, 8x8 microtile, register-prefetch pipeline.
// Output routed: q -> g_q [bh][n][d], k -> g_kt [bh][d][n], v -> g_v.
// ---------------------------------------------------------------------------
#define AS_STRIDE 132

__global__ void __launch_bounds__(256) qkv_gemm_kernel(
    const float* __restrict__ x, const float* __restrict__ vp,
    const float* __restrict__ w, const float* __restrict__ bias)
{
    __shared__ float As[16 * AS_STRIDE];   // As[kk][m]
    __shared__ float Bs[16 * 128];         // Bs[kk][nc]

    const int m0 = blockIdx.y * 128;
    const int n0 = blockIdx.x * 128;
    const int tid = threadIdx.x;
    const int tx = tid & 15, ty = tid >> 4;

    // A-load mapping: thread -> row (tid&127), k-quads u0 and u0+2
    const int am = tid & 127;
    const int u0 = tid >> 7;                 // 0 or 1
    int m_g = m0 + am; if (m_g > MTOT - 1) m_g = MTOT - 1;
    const int ab = m_g / NSEQ, an = m_g % NSEQ;
    const float* aptr = (an < NTOK)
        ? (vp + ((size_t)ab * NTOK + an) * CDIM)
        : (x + ((size_t)ab * 1024 + (an - NTOK)) * CDIM);

    // B-load mapping: rows kb, kb+8 ; col quad nq
    const int kb = tid >> 5;                 // 0..7
    const int nq = tid & 31;                 // 0..31
    const float* bptr = w + n0 + 4 * nq;

    float acc[8][8] = {};

    // prefetch tile 0
    float4 av0 = *(const float4*)(aptr + 4 * u0);
    float4 av1 = *(const float4*)(aptr + 4 * u0 + 8);
    float4 bv0 = *(const float4*)(bptr + (size_t)kb * 2304);
    float4 bv1 = *(const float4*)(bptr + (size_t)(kb + 8) * 2304);

    for (int k0 = 0; k0 < CDIM; k0 += 16) {
        __syncthreads();
        As[(4 * u0 + 0) * AS_STRIDE + am] = av0.x;
        As[(4 * u0 + 1) * AS_STRIDE + am] = av0.y;
        As[(4 * u0 + 2) * AS_STRIDE + am] = av0.z;
        As[(4 * u0 + 3) * AS_STRIDE + am] = av0.w;
        As[(4 * u0 + 8) * AS_STRIDE + am] = av1.x;
        As[(4 * u0 + 9) * AS_STRIDE + am] = av1.y;
        As[(4 * u0 + 10) * AS_STRIDE + am] = av1.z;
        As[(4 * u0 + 11) * AS_STRIDE + am] = av1.w;
        *(float4*)&Bs[kb * 128 + 4 * nq] = bv0;
        *(float4*)&Bs[(kb + 8) * 128 + 4 * nq] = bv1;
        __syncthreads();

        // prefetch next tile (clamped to 0 on last iter; loads stay in-bounds,
        // results unused) -- overlaps LDG latency with the FFMA block below.
        {
            const int kn = (k0 + 16 < CDIM) ? (k0 + 16) : 0;
            av0 = *(const float4*)(aptr + kn + 4 * u0);
            av1 = *(const float4*)(aptr + kn + 4 * u0 + 8);
            bv0 = *(const float4*)(bptr + (size_t)(kn + kb) * 2304);
            bv1 = *(const float4*)(bptr + (size_t)(kn + kb + 8) * 2304);
        }

#pragma unroll
        for (int kk = 0; kk < 16; kk++) {
            float a[8], b[8];
            *(float4*)&a[0] = *(const float4*)&As[kk * AS_STRIDE + 8 * ty];
            *(float4*)&a[4] = *(const float4*)&As[kk * AS_STRIDE + 8 * ty + 4];
            *(float4*)&b[0] = *(const float4*)&Bs[kk * 128 + 8 * tx];
            *(float4*)&b[4] = *(const float4*)&Bs[kk * 128 + 8 * tx + 4];
#pragma unroll
            for (int i = 0; i < 8; i++)
#pragma unroll
                for (int j = 0; j < 8; j++)
                    acc[i][j] += a[i] * b[j];
        }
    }

    // Store with q/k/v routing
#pragma unroll
    for (int i = 0; i < 8; i++) {
        int m = m0 + 8 * ty + i;
        if (m >= MTOT) break;
        int b = m / NSEQ, n = m % NSEQ;
#pragma unroll
        for (int jq = 0; jq < 2; jq++) {
            int col0 = n0 + 8 * tx + 4 * jq;             // 4-col quad, same 64-block
            float4 v4 = make_float4(acc[i][4 * jq + 0] + bias[col0 + 0],
                                    acc[i][4 * jq + 1] + bias[col0 + 1],
                                    acc[i][4 * jq + 2] + bias[col0 + 2],
                                    acc[i][4 * jq + 3] + bias[col0 + 3]);
            if (col0 < CDIM) {                           // Q
                int head = col0 >> 6, d0 = col0 & 63;
                *(float4*)&g_q[(((size_t)(b * NHEAD + head)) * NSEQ + n) * HDIM + d0] = v4;
            } else if (col0 < 2 * CDIM) {                // K -> transposed
                int c2 = col0 - CDIM;
                int head = c2 >> 6, d0 = c2 & 63;
                size_t base = ((size_t)(b * NHEAD + head)) * HDIM;
                g_kt[(base + d0 + 0) * NSEQ + n] = v4.x;
                g_kt[(base + d0 + 1) * NSEQ + n] = v4.y;
                g_kt[(base + d0 + 2) * NSEQ + n] = v4.z;
                g_kt[(base + d0 + 3) * NSEQ + n] = v4.w;
            } else {                                     // V
                int c2 = col0 - 2 * CDIM;
                int head = c2 >> 6, d0 = c2 & 63;
                *(float4*)&g_v[(((size_t)(b * NHEAD + head)) * NSEQ + n) * HDIM + d0] = v4;
            }
        }
    }
}

// ---------------------------------------------------------------------------
// Kernel 2: rel position projections.
// ---------------------------------------------------------------------------
__global__ void __launch_bounds__(256) rel_kernel(
    const float* __restrict__ rph, const float* __restrict__ rpw)
{
    const int h = blockIdx.x;
    const int bh = blockIdx.y;
    __shared__ float qs[32 * 64];

    for (int e = threadIdx.x; e < 32 * 64; e += 256) {
        int wq = e >> 6, c = e & 63;
        qs[e] = g_q[(((size_t)bh) * NSEQ + NTOK + h * 32 + wq) * HDIM + c];
    }
    __syncthreads();

#pragma unroll
    for (int t = 0; t < 4; t++) {
        int idx = threadIdx.x + t * 256;       // 0..1023
        int wq = idx >> 5, kk = idx & 31;
        const float* rh = rph + (h - kk + 31) * HDIM;
        const float* rw = rpw + (wq - kk + 31) * HDIM;
        float sh = 0.f, sw = 0.f;
#pragma unroll
        for (int c = 0; c < HDIM; c++) {
            float qv = qs[wq * 64 + c];
            sh += qv * rh[c];
            sw += qv * rw[c];
        }
        size_t base = ((((size_t)bh * 32 + h) * 32 + wq) * 32 + kk);
        g_relh[base] = sh;
        g_relw[base] = sw;
    }
}

// ---------------------------------------------------------------------------
// Kernel 3: attention.  One block = (bh, 32-query tile). 256 threads.
//
// SMEM layout (floats):
//   sc     [32][1036]           scores / probs            offset 0
//   relbuf [32][64]             per-qrow bias rows        offset 33152
//   qst    [64][36]             Q c-major (transposed)    offset 35200
//   kst    [64][132]            K c-major                 offset 37504
//   vs  = alias of kst region   V row-major [32][68]      (phase 3)
//   red = alias of relbuf+qst[0:512]  reduction [128][20] (ends 35712)
//   sinv  32 floats at 36224; smax 32 floats at 36256 (dead qst tail)
// Total 45952 floats = 183808 bytes -> 1 CTA/SM.
// ---------------------------------------------------------------------------
#define SC_STRIDE  1036
#define QT_STRIDE  36
#define KT_STRIDE  132
#define VS_STRIDE  68
#define RED_STRIDE 20
#define OFF_REL  33152
#define OFF_QT   35200
#define OFF_SINV 36224
#define OFF_SMAX 36256
#define OFF_KT   37504
#define ATTN_SMEM_FLOATS (OFF_KT + 64 * KT_STRIDE)
#define ATTN_SMEM_BYTES  (ATTN_SMEM_FLOATS * 4)

__global__ void __launch_bounds__(256) attn_kernel()
{
    extern __shared__ float smem[];
    float* sc     = smem;
    float* relbuf = smem + OFF_REL;
    float* qst    = smem + OFF_QT;
    float* kst    = smem + OFF_KT;
    float* vs     = smem + OFF_KT;     // phase-3 alias
    float* red    = smem + OFF_REL;    // phase-3 alias (2560 floats, ends 35712)
    float* sinv   = smem + OFF_SINV;   // per-row 1/sum (32 floats)
    float* smax   = smem + OFF_SMAX;   // per-row max, fused from phase 1

    const int qt = blockIdx.x;
    const int bh = blockIdx.y;
    const int q0 = qt * 32;
    const int tid = threadIdx.x;

    // ---- load Q tile transposed (c-major) + rel bias rows ----
    for (int e = tid; e < 32 * 64; e += 256) {
        int i = e >> 6, c = e & 63;
        int qi = q0 + i;
        qst[c * QT_STRIDE + i] = (qi < NSEQ)
            ? g_q[(((size_t)bh) * NSEQ + qi) * HDIM + c] : 0.f;
    }
    // relbuf[i][0..31] = rel_h row, relbuf[i][32..63] = rel_w row (image rows only)
    for (int e = tid; e < 32 * 64; e += 256) {
        int i = e >> 6, c = e & 63;
        int qi = q0 + i;
        float v = 0.f;
        if (qi >= NTOK && qi < NSEQ) {
            int qh = (qi - NTOK) >> 5, qw = (qi - NTOK) & 31;
            size_t bb = (((size_t)bh * 32 + qh) * 32 + qw) * 32;
            v = (c < 32) ? g_relh[bb + c] : g_relw[bb + (c - 32)];
        }
        relbuf[i * 64 + c] = v;
    }
    __syncthreads();

    // ---- Phase 1: S = scale*Q K^T + bias, with fused per-row max tracking ----
    {
        const int tx = tid & 31;       // k-group (lane)
        const int ty = tid >> 5;       // q-group (warp id) -> Q reads broadcast
        // loader mapping: e2 = tid + u*256 -> c = e2>>5 (0..63), jq = e2&31 (j=4*jq)
        const int lc0 = tid >> 5;      // c for u=0 is (tid+u*256)>>5 = lc0 + 8*u
        const int ljq = tid & 31;

        float rmax[4] = {-1e30f, -1e30f, -1e30f, -1e30f};

        float4 kpre[8];
#pragma unroll
        for (int u = 0; u < 8; u++) {
            int c = lc0 + 8 * u;
            int kj = 4 * ljq;          // tile 0: kbase = 0
            kpre[u] = (kj < NSEQ)
                ? *(const float4*)&g_kt[(((size_t)bh) * HDIM + c) * NSEQ + kj]
                : make_float4(0.f, 0.f, 0.f, 0.f);
        }

        for (int kt = 0; kt < 9; kt++) {
            const int kbase = kt * 128;
            // publish prefetched tile
#pragma unroll
            for (int u = 0; u < 8; u++) {
                int c = lc0 + 8 * u;
                *(float4*)&kst[c * KT_STRIDE + 4 * ljq] = kpre[u];
            }
            __syncthreads();

            // prefetch next tile (overlaps with compute below)
            if (kt < 8) {
                const int nbase = kbase + 128;
#pragma unroll
                for (int u = 0; u < 8; u++) {
                    int c = lc0 + 8 * u;
                    int kj = nbase + 4 * ljq;
                    kpre[u] = (kj < NSEQ)
                        ? *(const float4*)&g_kt[(((size_t)bh) * HDIM + c) * NSEQ + kj]
                        : make_float4(0.f, 0.f, 0.f, 0.f);
                }
            }

            float acc[4][4] = {};
#pragma unroll 16
            for (int c = 0; c < 64; c++) {
                float4 qv = *(const float4*)&qst[c * QT_STRIDE + 4 * ty];
                float4 kv = *(const float4*)&kst[c * KT_STRIDE + 4 * tx];
                acc[0][0] += qv.x * kv.x; acc[0][1] += qv.x * kv.y; acc[0][2] += qv.x * kv.z; acc[0][3] += qv.x * kv.w;
                acc[1][0] += qv.y * kv.x; acc[1][1] += qv.y * kv.y; acc[1][2] += qv.y * kv.z; acc[1][3] += qv.y * kv.w;
                acc[2][0] += qv.z * kv.x; acc[2][1] += qv.z * kv.y; acc[2][2] += qv.z * kv.z; acc[2][3] += qv.z * kv.w;
                acc[3][0] += qv.w * kv.x; acc[3][1] += qv.w * kv.y; acc[3][2] += qv.w * kv.z; acc[3][3] += qv.w * kv.w;
            }

            // Epilogue. Quads are 4-aligned and NTOK=8, 32 are multiples of 4, so:
            //  - the kj<NTOK mask is uniform across the quad,
            //  - (kj-NTOK)>>5 (rel_h idx) is constant across the quad,
            //  - the 4 rel_w values are consecutive & float4-aligned.
            const int kj0 = kbase + 4 * tx;
            if (kj0 + 3 < NSEQ) {              // NSEQ multiple of 4: quads all-or-nothing
                const bool qmask = (kj0 < NTOK);
                const int off0 = kj0 - NTOK;   // valid when !qmask
#pragma unroll
                for (int ii = 0; ii < 4; ii++) {
                    int i = 4 * ty + ii;
                    int qi = q0 + i;
                    if (qi >= NSEQ) continue;
                    float4 sv = make_float4(acc[ii][0] * QKSCALE, acc[ii][1] * QKSCALE,
                                            acc[ii][2] * QKSCALE, acc[ii][3] * QKSCALE);
                    if (qi >= NTOK) {
                        if (qmask) {
                            sv.x += -100.f; sv.y += -100.f; sv.z += -100.f; sv.w += -100.f;
                        } else {
                            float rh = relbuf[i * 64 + (off0 >> 5)];
                            float4 rw = *(const float4*)&relbuf[i * 64 + 32 + (off0 & 31)];
                            sv.x += rh + rw.x; sv.y += rh + rw.y;
                            sv.z += rh + rw.z; sv.w += rh + rw.w;
                        }
                    }
                    rmax[ii] = fmaxf(rmax[ii],
                                     fmaxf(fmaxf(sv.x, sv.y), fmaxf(sv.z, sv.w)));
                    *(float4*)&sc[i * SC_STRIDE + kj0] = sv;
                }
            }
            __syncthreads();
        }

        // Warp-reduce row maxima: warp ty's 32 lanes cover all columns of
        // rows 4ty..4ty+3, so the reduction over lanes is the exact row max.
#pragma unroll
        for (int ii = 0; ii < 4; ii++) {
            float m = rmax[ii];
#pragma unroll
            for (int o = 16; o > 0; o >>= 1)
                m = fmaxf(m, __shfl_xor_sync(0xffffffffu, m, o));
            if (tx == 0) smax[4 * ty + ii] = m;
        }
    }
    __syncthreads();

    // ---- prefetch first V tile (registers only; vs smem still holds K) ----
    // loader mapping: e2 = tid + u*256 -> j = e2>>4 (0..31), cq = e2&15 (c=4*cq)
    const int vlj0 = tid >> 4;          // j for u=0 ; u=1 adds 16
    const int vlcq = tid & 15;
    float4 vpre[2];
#pragma unroll
    for (int u = 0; u < 2; u++) {
        int j = vlj0 + 16 * u;
        vpre[u] = *(const float4*)&g_v[(((size_t)bh) * NSEQ + j) * HDIM + 4 * vlcq];
    }

    // ---- Phase 2: exp + sum only (max fused into phase 1, norm deferred) ----
    {
        const int warp = tid >> 5, lane = tid & 31;
        for (int i = warp; i < 32; i += 8) {
            if (q0 + i >= NSEQ) continue;
            float* row = sc + i * SC_STRIDE;
            const float m = smax[i];
            float sum = 0.f;
            for (int t = 0; t < 33; t++) {
                int j = lane + t * 32;
                if (j < NSEQ) {
                    float e = __expf(row[j] - m);
                    row[j] = e;
                    sum += e;
                }
            }
#pragma unroll
            for (int o = 16; o > 0; o >>= 1)
                sum += __shfl_xor_sync(0xffffffffu, sum, o);
            if (lane == 0) sinv[i] = 1.f / sum;   // applied in phase-3 epilogue
        }
    }
    __syncthreads();

    // ---- Phase 3: O = (P_unnorm V) * sinv.  4q x 4d microtile, halves split j-quads ----
    {
        const int half = tid >> 7;          // 0 or 1
        const int ph = tid & 127;
        const int qg = ph >> 4;             // q-group 0..7 -> rows 4qg..4qg+3
        const int dg = ph & 15;             // d-group 0..15 -> cols 4dg..4dg+3
        float oacc[4][4] = {};

        for (int kt = 0; kt < 33; kt++) {
            const int kbase = kt * 32;
            const int jmax = (NSEQ - kbase < 32) ? (NSEQ - kbase) : 32;  // 32 or 8
            // publish prefetched V tile
#pragma unroll
            for (int u = 0; u < 2; u++) {
                int j = vlj0 + 16 * u;
                *(float4*)&vs[j * VS_STRIDE + 4 * vlcq] = vpre[u];
            }
            __syncthreads();

            // prefetch next V tile
            if (kt < 32) {
                const int nbase = kbase + 32;
#pragma unroll
                for (int u = 0; u < 2; u++) {
                    int j = vlj0 + 16 * u;
                    int kj = nbase + j;
                    vpre[u] = (kj < NSEQ)
                        ? *(const float4*)&g_v[(((size_t)bh) * NSEQ + kj) * HDIM + 4 * vlcq]
                        : make_float4(0.f, 0.f, 0.f, 0.f);
                }
            }

            const int nquad = jmax >> 2;    // 8 or 2
            for (int qd = half; qd < nquad; qd += 2) {
                const int j0 = kbase + 4 * qd;   // column in sc
                const int jl = 4 * qd;           // local row in vs
                float4 p4[4];
#pragma unroll
                for (int r = 0; r < 4; r++)
                    p4[r] = *(const float4*)&sc[(4 * qg + r) * SC_STRIDE + j0];
                const float* p0 = (const float*)&p4[0];
                const float* p1 = (const float*)&p4[1];
                const float* p2 = (const float*)&p4[2];
                const float* p3 = (const float*)&p4[3];
#pragma unroll
                for (int jj = 0; jj < 4; jj++) {
                    float4 vv = *(const float4*)&vs[(jl + jj) * VS_STRIDE + 4 * dg];
                    float w0 = p0[jj], w1 = p1[jj], w2 = p2[jj], w3 = p3[jj];
                    oacc[0][0] += w0 * vv.x; oacc[0][1] += w0 * vv.y; oacc[0][2] += w0 * vv.z; oacc[0][3] += w0 * vv.w;
                    oacc[1][0] += w1 * vv.x; oacc[1][1] += w1 * vv.y; oacc[1][2] += w1 * vv.z; oacc[1][3] += w1 * vv.w;
                    oacc[2][0] += w2 * vv.x; oacc[2][1] += w2 * vv.y; oacc[2][2] += w2 * vv.z; oacc[2][3] += w2 * vv.w;
                    oacc[3][0] += w3 * vv.x; oacc[3][1] += w3 * vv.y; oacc[3][2] += w3 * vv.z; oacc[3][3] += w3 * vv.w;
                }
            }
            __syncthreads();
        }

        // combine halves; apply deferred softmax normalization at the single
        // point where each output element is produced.
        if (half == 1) {
#pragma unroll
            for (int r = 0; r < 4; r++)
                *(float4*)&red[ph * RED_STRIDE + 4 * r] =
                    make_float4(oacc[r][0], oacc[r][1], oacc[r][2], oacc[r][3]);
        }
        __syncthreads();
        if (half == 0) {
            const int b = bh / NHEAD, head = bh % NHEAD;
#pragma unroll
            for (int r = 0; r < 4; r++) {
                float4 o2 = *(const float4*)&red[ph * RED_STRIDE + 4 * r];
                int qi = q0 + 4 * qg + r;
                if (qi < NSEQ) {
                    float inv = sinv[4 * qg + r];
                    float4 ov = make_float4((oacc[r][0] + o2.x) * inv,
                                            (oacc[r][1] + o2.y) * inv,
                                            (oacc[r][2] + o2.z) * inv,
                                            (oacc[r][3] + o2.w) * inv);
                    *(float4*)&g_o[((size_t)(b * NSEQ + qi)) * CDIM + head * HDIM + 4 * dg] = ov;
                }
            }
        }
    }
}

// ---------------------------------------------------------------------------
// Kernel 4: proj GEMM. out[m][j] = g_o[m][:] @ proj_w[:, j] + proj_b[j]
// 128x128 tile, BK=16, 8x8 microtile, register-prefetch pipeline.
// ---------------------------------------------------------------------------
__global__ void __launch_bounds__(256) proj_gemm_kernel(
    const float* __restrict__ w, const float* __restrict__ bias,
    float* __restrict__ out)
{
    __shared__ float As[16 * AS_STRIDE];
    __shared__ float Bs[16 * 128];

    const int m0 = blockIdx.y * 128;
    const int n0 = blockIdx.x * 128;
    const int tid = threadIdx.x;
    const int tx = tid & 15, ty = tid >> 4;

    const int am = tid & 127;
    const int u0 = tid >> 7;
    int m_g = m0 + am; if (m_g > MTOT - 1) m_g = MTOT - 1;
    const float* aptr = g_o + (size_t)m_g * CDIM;

    const int kb = tid >> 5;
    const int nq = tid & 31;
    const float* bptr = w + n0 + 4 * nq;

    float acc[8][8] = {};

    // prefetch tile 0
    float4 av0 = *(const float4*)(aptr + 4 * u0);
    float4 av1 = *(const float4*)(aptr + 4 * u0 + 8);
    float4 bv0 = *(const float4*)(bptr + (size_t)kb * CDIM);
    float4 bv1 = *(const float4*)(bptr + (size_t)(kb + 8) * CDIM);

    for (int k0 = 0; k0 < CDIM; k0 += 16) {
        __syncthreads();
        As[(4 * u0 + 0) * AS_STRIDE + am] = av0.x;
        As[(4 * u0 + 1) * AS_STRIDE + am] = av0.y;
        As[(4 * u0 + 2) * AS_STRIDE + am] = av0.z;
        As[(4 * u0 + 3) * AS_STRIDE + am] = av0.w;
        As[(4 * u0 + 8) * AS_STRIDE + am] = av1.x;
        As[(4 * u0 + 9) * AS_STRIDE + am] = av1.y;
        As[(4 * u0 + 10) * AS_STRIDE + am] = av1.z;
        As[(4 * u0 + 11) * AS_STRIDE + am] = av1.w;
        *(float4*)&Bs[kb * 128 + 4 * nq] = bv0;
        *(float4*)&Bs[(kb + 8) * 128 + 4 * nq] = bv1;
        __syncthreads();

        // prefetch next tile (clamped; overlaps compute)
        {
            const int kn = (k0 + 16 < CDIM) ? (k0 + 16) : 0;
            av0 = *(const float4*)(aptr + kn + 4 * u0);
            av1 = *(const float4*)(aptr + kn + 4 * u0 + 8);
            bv0 = *(const float4*)(bptr + (size_t)(kn + kb) * CDIM);
            bv1 = *(const float4*)(bptr + (size_t)(kn + kb + 8) * CDIM);
        }

#pragma unroll
        for (int kk = 0; kk < 16; kk++) {
            float a[8], b[8];
            *(float4*)&a[0] = *(const float4*)&As[kk * AS_STRIDE + 8 * ty];
            *(float4*)&a[4] = *(const float4*)&As[kk * AS_STRIDE + 8 * ty + 4];
            *(float4*)&b[0] = *(const float4*)&Bs[kk * 128 + 8 * tx];
            *(float4*)&b[4] = *(const float4*)&Bs[kk * 128 + 8 * tx + 4];
#pragma unroll
            for (int i = 0; i < 8; i++)
#pragma unroll
                for (int j = 0; j < 8; j++)
                    acc[i][j] += a[i] * b[j];
        }
    }

    const size_t vp_base = (size_t)BATCH * 1024 * CDIM;   // 6291456
#pragma unroll
    for (int i = 0; i < 8; i++) {
        int m = m0 + 8 * ty + i;
        if (m >= MTOT) break;
        int b = m / NSEQ, n = m % NSEQ;
        size_t rowbase = (n < NTOK)
            ? vp_base + ((size_t)(b * NTOK + n)) * CDIM
            : ((size_t)(b * 1024 + (n - NTOK))) * CDIM;
#pragma unroll
        for (int jq = 0; jq < 2; jq++) {
            int col0 = n0 + 8 * tx + 4 * jq;
            float4 v4 = make_float4(acc[i][4 * jq + 0] + bias[col0 + 0],
                                    acc[i][4 * jq + 1] + bias[col0 + 1],
                                    acc[i][4 * jq + 2] + bias[col0 + 2],
                                    acc[i][4 * jq + 3] + bias[col0 + 3]);
            *(float4*)&out[rowbase + col0] = v4;
        }
    }
}

// ---------------------------------------------------------------------------
extern "C" void kernel_launch(void* const* d_in, const int* in_sizes, int n_in,
                              void* d_out, int out_size)
{
    const float* x      = (const float*)d_in[0];
    const float* vp     = (const float*)d_in[1];
    const float* qkv_w  = (const float*)d_in[2];
    const float* qkv_b  = (const float*)d_in[3];
    const float* proj_w = (const float*)d_in[4];
    const float* proj_b = (const float*)d_in[5];
    const float* rph    = (const float*)d_in[6];
    const float* rpw    = (const float*)d_in[7];
    float* out = (float*)d_out;

    cudaFuncSetAttribute(attn_kernel,
                         cudaFuncAttributeMaxDynamicSharedMemorySize,
                         ATTN_SMEM_BYTES);

    qkv_gemm_kernel<<<dim3(18, 65), 256>>>(x, vp, qkv_w, qkv_b);
    rel_kernel<<<dim3(32, 96), 256>>>(rph, rpw);
    attn_kernel<<<dim3(33, 96), 256, ATTN_SMEM_BYTES>>>();
    proj_gemm_kernel<<<dim3(6, 65), 256>>>(proj_w, proj_b, out);
}

// round 11
// speedup vs baseline: 1.0376x; 1.0376x over previous
#include <cuda_runtime.h>
#include <math.h>

// Problem constants
#define BATCH   8
#define HGT     32
#define WID     32
#define CDIM    768
#define NHEAD   12
#define HDIM    64
#define NTOK    8
#define NSEQ    1032            // H*W + NT
#define BNH     96              // BATCH*NHEAD
#define MTOT    8256            // BATCH*NSEQ
#define QKSCALE 0.125f          // hd^-0.5

typedef unsigned long long u64;

// Packed fp32x2 FMA (sm_100+): fills the 128-lane fp32 datapath; scalar
// 3-reg FFMA only reaches 64 lanes/SM/cyc (rt_SMSP=2).
#define F32X2_FMA(d, a, b, c) \
    asm("fma.rn.f32x2 %0, %1, %2, %3;" : "=l"(d) : "l"(a), "l"(b), "l"(c))
#define F32X2_DUP(d, x) \
    do { unsigned _xi = __float_as_uint(x); \
         asm("mov.b64 %0, {%1, %1};" : "=l"(d) : "r"(_xi)); } while (0)
#define F32X2_UNPACK(lo, hi, p) \
    do { unsigned _lo, _hi; \
         asm("mov.b64 {%0, %1}, %2;" : "=r"(_lo), "=r"(_hi) : "l"(p)); \
         lo = __uint_as_float(_lo); hi = __uint_as_float(_hi); } while (0)

// Scratch (device globals; no allocation allowed)
__device__ float g_q [BNH * NSEQ * HDIM];         // [bh][n][d]
__device__ float g_kt[BNH * HDIM * NSEQ];         // [bh][d][n]  (transposed!)
__device__ float g_v [BNH * NSEQ * HDIM];         // [bh][n][d]
__device__ float g_o [BATCH * NSEQ * CDIM];       // [b][n][head*64+d]  (pre-proj)
__device__ float g_relh[BNH * 32 * 32 * 32];      // [bh][qh][qw][kh]
__device__ float g_relw[BNH * 32 * 32 * 32];      // [bh][qh][qw][kw]

// ---------------------------------------------------------------------------
// Kernel 1: QKV GEMM.  128x128 tile, BK=16, 8x8 microtile, f32x2 packed FMA.
// Output routed: q -> g_q [bh][n][d], k -> g_kt [bh][d][n], v -> g_v.
// ---------------------------------------------------------------------------
#define AS_STRIDE 132

__global__ void __launch_bounds__(256) qkv_gemm_kernel(
    const float* __restrict__ x, const float* __restrict__ vp,
    const float* __restrict__ w, const float* __restrict__ bias)
{
    __shared__ float As[16 * AS_STRIDE];   // As[kk][m]
    __shared__ float Bs[16 * 128];         // Bs[kk][nc]

    const int m0 = blockIdx.y * 128;
    const int n0 = blockIdx.x * 128;
    const int tid = threadIdx.x;
    const int tx = tid & 15, ty = tid >> 4;

    const int am = tid & 127;
    const int u0 = tid >> 7;                 // 0 or 1
    int m_g = m0 + am; if (m_g > MTOT - 1) m_g = MTOT - 1;
    const int ab = m_g / NSEQ, an = m_g % NSEQ;
    const float* aptr = (an < NTOK)
        ? (vp + ((size_t)ab * NTOK + an) * CDIM)
        : (x + ((size_t)ab * 1024 + (an - NTOK)) * CDIM);

    const int kb = tid >> 5;                 // 0..7
    const int nq = tid & 31;                 // 0..31
    const float* bptr = w + n0 + 4 * nq;

    u64 acc2[8][4];
#pragma unroll
    for (int i = 0; i < 8; i++)
#pragma unroll
        for (int j = 0; j < 4; j++) acc2[i][j] = 0ULL;

    // prefetch tile 0
    float4 av0 = *(const float4*)(aptr + 4 * u0);
    float4 av1 = *(const float4*)(aptr + 4 * u0 + 8);
    float4 bv0 = *(const float4*)(bptr + (size_t)kb * 2304);
    float4 bv1 = *(const float4*)(bptr + (size_t)(kb + 8) * 2304);

    for (int k0 = 0; k0 < CDIM; k0 += 16) {
        __syncthreads();
        As[(4 * u0 + 0) * AS_STRIDE + am] = av0.x;
        As[(4 * u0 + 1) * AS_STRIDE + am] = av0.y;
        As[(4 * u0 + 2) * AS_STRIDE + am] = av0.z;
        As[(4 * u0 + 3) * AS_STRIDE + am] = av0.w;
        As[(4 * u0 + 8) * AS_STRIDE + am] = av1.x;
        As[(4 * u0 + 9) * AS_STRIDE + am] = av1.y;
        As[(4 * u0 + 10) * AS_STRIDE + am] = av1.z;
        As[(4 * u0 + 11) * AS_STRIDE + am] = av1.w;
        *(float4*)&Bs[kb * 128 + 4 * nq] = bv0;
        *(float4*)&Bs[(kb + 8) * 128 + 4 * nq] = bv1;
        __syncthreads();

        // prefetch next tile (clamped; overlaps compute)
        {
            const int kn = (k0 + 16 < CDIM) ? (k0 + 16) : 0;
            av0 = *(const float4*)(aptr + kn + 4 * u0);
            av1 = *(const float4*)(aptr + kn + 4 * u0 + 8);
            bv0 = *(const float4*)(bptr + (size_t)(kn + kb) * 2304);
            bv1 = *(const float4*)(bptr + (size_t)(kn + kb + 8) * 2304);
        }

#pragma unroll
        for (int kk = 0; kk < 16; kk++) {
            float a[8];
            *(float4*)&a[0] = *(const float4*)&As[kk * AS_STRIDE + 8 * ty];
            *(float4*)&a[4] = *(const float4*)&As[kk * AS_STRIDE + 8 * ty + 4];
            ulonglong2 bl = *(const ulonglong2*)&Bs[kk * 128 + 8 * tx];
            ulonglong2 bh = *(const ulonglong2*)&Bs[kk * 128 + 8 * tx + 4];
#pragma unroll
            for (int i = 0; i < 8; i++) {
                u64 ad; F32X2_DUP(ad, a[i]);
                F32X2_FMA(acc2[i][0], ad, bl.x, acc2[i][0]);
                F32X2_FMA(acc2[i][1], ad, bl.y, acc2[i][1]);
                F32X2_FMA(acc2[i][2], ad, bh.x, acc2[i][2]);
                F32X2_FMA(acc2[i][3], ad, bh.y, acc2[i][3]);
            }
        }
    }

    // unpack packed accumulators (each component is one output's full sum)
    float acc[8][8];
#pragma unroll
    for (int i = 0; i < 8; i++)
#pragma unroll
        for (int j = 0; j < 4; j++)
            F32X2_UNPACK(acc[i][2 * j], acc[i][2 * j + 1], acc2[i][j]);

    // Store with q/k/v routing
#pragma unroll
    for (int i = 0; i < 8; i++) {
        int m = m0 + 8 * ty + i;
        if (m >= MTOT) break;
        int b = m / NSEQ, n = m % NSEQ;
#pragma unroll
        for (int jq = 0; jq < 2; jq++) {
            int col0 = n0 + 8 * tx + 4 * jq;             // 4-col quad, same 64-block
            float4 v4 = make_float4(acc[i][4 * jq + 0] + bias[col0 + 0],
                                    acc[i][4 * jq + 1] + bias[col0 + 1],
                                    acc[i][4 * jq + 2] + bias[col0 + 2],
                                    acc[i][4 * jq + 3] + bias[col0 + 3]);
            if (col0 < CDIM) {                           // Q
                int head = col0 >> 6, d0 = col0 & 63;
                *(float4*)&g_q[(((size_t)(b * NHEAD + head)) * NSEQ + n) * HDIM + d0] = v4;
            } else if (col0 < 2 * CDIM) {                // K -> transposed
                int c2 = col0 - CDIM;
                int head = c2 >> 6, d0 = c2 & 63;
                size_t base = ((size_t)(b * NHEAD + head)) * HDIM;
                g_kt[(base + d0 + 0) * NSEQ + n] = v4.x;
                g_kt[(base + d0 + 1) * NSEQ + n] = v4.y;
                g_kt[(base + d0 + 2) * NSEQ + n] = v4.z;
                g_kt[(base + d0 + 3) * NSEQ + n] = v4.w;
            } else {                                     // V
                int c2 = col0 - 2 * CDIM;
                int head = c2 >> 6, d0 = c2 & 63;
                *(float4*)&g_v[(((size_t)(b * NHEAD + head)) * NSEQ + n) * HDIM + d0] = v4;
            }
        }
    }
}

// ---------------------------------------------------------------------------
// Kernel 2: rel position projections.
// ---------------------------------------------------------------------------
__global__ void __launch_bounds__(256) rel_kernel(
    const float* __restrict__ rph, const float* __restrict__ rpw)
{
    const int h = blockIdx.x;
    const int bh = blockIdx.y;
    __shared__ float qs[32 * 64];

    for (int e = threadIdx.x; e < 32 * 64; e += 256) {
        int wq = e >> 6, c = e & 63;
        qs[e] = g_q[(((size_t)bh) * NSEQ + NTOK + h * 32 + wq) * HDIM + c];
    }
    __syncthreads();

#pragma unroll
    for (int t = 0; t < 4; t++) {
        int idx = threadIdx.x + t * 256;       // 0..1023
        int wq = idx >> 5, kk = idx & 31;
        const float* rh = rph + (h - kk + 31) * HDIM;
        const float* rw = rpw + (wq - kk + 31) * HDIM;
        float sh = 0.f, sw = 0.f;
#pragma unroll
        for (int c = 0; c < HDIM; c++) {
            float qv = qs[wq * 64 + c];
            sh += qv * rh[c];
            sw += qv * rw[c];
        }
        size_t base = ((((size_t)bh * 32 + h) * 32 + wq) * 32 + kk);
        g_relh[base] = sh;
        g_relw[base] = sw;
    }
}

// ---------------------------------------------------------------------------
// Kernel 3: attention.  One block = (bh, 32-query tile). 256 threads.
// SMEM layout as before (183808 bytes -> 1 CTA/SM).
// ---------------------------------------------------------------------------
#define SC_STRIDE  1036
#define QT_STRIDE  36
#define KT_STRIDE  132
#define VS_STRIDE  68
#define RED_STRIDE 20
#define OFF_REL  33152
#define OFF_QT   35200
#define OFF_SINV 36224
#define OFF_SMAX 36256
#define OFF_KT   37504
#define ATTN_SMEM_FLOATS (OFF_KT + 64 * KT_STRIDE)
#define ATTN_SMEM_BYTES  (ATTN_SMEM_FLOATS * 4)

__global__ void __launch_bounds__(256) attn_kernel()
{
    extern __shared__ float smem[];
    float* sc     = smem;
    float* relbuf = smem + OFF_REL;
    float* qst    = smem + OFF_QT;
    float* kst    = smem + OFF_KT;
    float* vs     = smem + OFF_KT;     // phase-3 alias
    float* red    = smem + OFF_REL;    // phase-3 alias (2560 floats, ends 35712)
    float* sinv   = smem + OFF_SINV;   // per-row 1/sum (32 floats)
    float* smax   = smem + OFF_SMAX;   // per-row max, fused from phase 1

    const int qt = blockIdx.x;
    const int bh = blockIdx.y;
    const int q0 = qt * 32;
    const int tid = threadIdx.x;

    // ---- load Q tile transposed (c-major) + rel bias rows ----
    for (int e = tid; e < 32 * 64; e += 256) {
        int i = e >> 6, c = e & 63;
        int qi = q0 + i;
        qst[c * QT_STRIDE + i] = (qi < NSEQ)
            ? g_q[(((size_t)bh) * NSEQ + qi) * HDIM + c] : 0.f;
    }
    for (int e = tid; e < 32 * 64; e += 256) {
        int i = e >> 6, c = e & 63;
        int qi = q0 + i;
        float v = 0.f;
        if (qi >= NTOK && qi < NSEQ) {
            int qh = (qi - NTOK) >> 5, qw = (qi - NTOK) & 31;
            size_t bb = (((size_t)bh * 32 + qh) * 32 + qw) * 32;
            v = (c < 32) ? g_relh[bb + c] : g_relw[bb + (c - 32)];
        }
        relbuf[i * 64 + c] = v;
    }
    __syncthreads();

    // ---- Phase 1: S = scale*Q K^T + bias, fused row max, f32x2 FMA ----
    {
        const int tx = tid & 31;       // k-group (lane)
        const int ty = tid >> 5;       // q-group (warp id) -> Q reads broadcast
        const int lc0 = tid >> 5;
        const int ljq = tid & 31;

        float rmax[4] = {-1e30f, -1e30f, -1e30f, -1e30f};

        float4 kpre[8];
#pragma unroll
        for (int u = 0; u < 8; u++) {
            int c = lc0 + 8 * u;
            int kj = 4 * ljq;
            kpre[u] = (kj < NSEQ)
                ? *(const float4*)&g_kt[(((size_t)bh) * HDIM + c) * NSEQ + kj]
                : make_float4(0.f, 0.f, 0.f, 0.f);
        }

        for (int kt = 0; kt < 9; kt++) {
            const int kbase = kt * 128;
#pragma unroll
            for (int u = 0; u < 8; u++) {
                int c = lc0 + 8 * u;
                *(float4*)&kst[c * KT_STRIDE + 4 * ljq] = kpre[u];
            }
            __syncthreads();

            if (kt < 8) {
                const int nbase = kbase + 128;
#pragma unroll
                for (int u = 0; u < 8; u++) {
                    int c = lc0 + 8 * u;
                    int kj = nbase + 4 * ljq;
                    kpre[u] = (kj < NSEQ)
                        ? *(const float4*)&g_kt[(((size_t)bh) * HDIM + c) * NSEQ + kj]
                        : make_float4(0.f, 0.f, 0.f, 0.f);
                }
            }

            u64 acc2[4][2];
#pragma unroll
            for (int i = 0; i < 4; i++) { acc2[i][0] = 0ULL; acc2[i][1] = 0ULL; }
#pragma unroll 16
            for (int c = 0; c < 64; c++) {
                float4 qv = *(const float4*)&qst[c * QT_STRIDE + 4 * ty];
                ulonglong2 kv = *(const ulonglong2*)&kst[c * KT_STRIDE + 4 * tx];
                u64 d0, d1, d2, d3;
                F32X2_DUP(d0, qv.x); F32X2_DUP(d1, qv.y);
                F32X2_DUP(d2, qv.z); F32X2_DUP(d3, qv.w);
                F32X2_FMA(acc2[0][0], d0, kv.x, acc2[0][0]);
                F32X2_FMA(acc2[0][1], d0, kv.y, acc2[0][1]);
                F32X2_FMA(acc2[1][0], d1, kv.x, acc2[1][0]);
                F32X2_FMA(acc2[1][1], d1, kv.y, acc2[1][1]);
                F32X2_FMA(acc2[2][0], d2, kv.x, acc2[2][0]);
                F32X2_FMA(acc2[2][1], d2, kv.y, acc2[2][1]);
                F32X2_FMA(acc2[3][0], d3, kv.x, acc2[3][0]);
                F32X2_FMA(acc2[3][1], d3, kv.y, acc2[3][1]);
            }
            float acc[4][4];
#pragma unroll
            for (int i = 0; i < 4; i++) {
                F32X2_UNPACK(acc[i][0], acc[i][1], acc2[i][0]);
                F32X2_UNPACK(acc[i][2], acc[i][3], acc2[i][1]);
            }

            // Epilogue (quad-uniform rel bias; see round-8 derivation)
            const int kj0 = kbase + 4 * tx;
            if (kj0 + 3 < NSEQ) {
                const bool qmask = (kj0 < NTOK);
                const int off0 = kj0 - NTOK;
#pragma unroll
                for (int ii = 0; ii < 4; ii++) {
                    int i = 4 * ty + ii;
                    int qi = q0 + i;
                    if (qi >= NSEQ) continue;
                    float4 sv = make_float4(acc[ii][0] * QKSCALE, acc[ii][1] * QKSCALE,
                                            acc[ii][2] * QKSCALE, acc[ii][3] * QKSCALE);
                    if (qi >= NTOK) {
                        if (qmask) {
                            sv.x += -100.f; sv.y += -100.f; sv.z += -100.f; sv.w += -100.f;
                        } else {
                            float rh = relbuf[i * 64 + (off0 >> 5)];
                            float4 rw = *(const float4*)&relbuf[i * 64 + 32 + (off0 & 31)];
                            sv.x += rh + rw.x; sv.y += rh + rw.y;
                            sv.z += rh + rw.z; sv.w += rh + rw.w;
                        }
                    }
                    rmax[ii] = fmaxf(rmax[ii],
                                     fmaxf(fmaxf(sv.x, sv.y), fmaxf(sv.z, sv.w)));
                    *(float4*)&sc[i * SC_STRIDE + kj0] = sv;
                }
            }
            __syncthreads();
        }

#pragma unroll
        for (int ii = 0; ii < 4; ii++) {
            float m = rmax[ii];
#pragma unroll
            for (int o = 16; o > 0; o >>= 1)
                m = fmaxf(m, __shfl_xor_sync(0xffffffffu, m, o));
            if (tx == 0) smax[4 * ty + ii] = m;
        }
    }
    __syncthreads();

    // ---- prefetch first V tile ----
    const int vlj0 = tid >> 4;
    const int vlcq = tid & 15;
    float4 vpre[2];
#pragma unroll
    for (int u = 0; u < 2; u++) {
        int j = vlj0 + 16 * u;
        vpre[u] = *(const float4*)&g_v[(((size_t)bh) * NSEQ + j) * HDIM + 4 * vlcq];
    }

    // ---- Phase 2: exp + sum only ----
    {
        const int warp = tid >> 5, lane = tid & 31;
        for (int i = warp; i < 32; i += 8) {
            if (q0 + i >= NSEQ) continue;
            float* row = sc + i * SC_STRIDE;
            const float m = smax[i];
            float sum = 0.f;
            for (int t = 0; t < 33; t++) {
                int j = lane + t * 32;
                if (j < NSEQ) {
                    float e = __expf(row[j] - m);
                    row[j] = e;
                    sum += e;
                }
            }
#pragma unroll
            for (int o = 16; o > 0; o >>= 1)
                sum += __shfl_xor_sync(0xffffffffu, sum, o);
            if (lane == 0) sinv[i] = 1.f / sum;
        }
    }
    __syncthreads();

    // ---- Phase 3: O = (P_unnorm V) * sinv, f32x2 packed over d ----
    {
        const int half = tid >> 7;
        const int ph = tid & 127;
        const int qg = ph >> 4;
        const int dg = ph & 15;
        u64 oacc2[4][2];
#pragma unroll
        for (int r = 0; r < 4; r++) { oacc2[r][0] = 0ULL; oacc2[r][1] = 0ULL; }

        for (int kt = 0; kt < 33; kt++) {
            const int kbase = kt * 32;
            const int jmax = (NSEQ - kbase < 32) ? (NSEQ - kbase) : 32;
#pragma unroll
            for (int u = 0; u < 2; u++) {
                int j = vlj0 + 16 * u;
                *(float4*)&vs[j * VS_STRIDE + 4 * vlcq] = vpre[u];
            }
            __syncthreads();

            if (kt < 32) {
                const int nbase = kbase + 32;
#pragma unroll
                for (int u = 0; u < 2; u++) {
                    int j = vlj0 + 16 * u;
                    int kj = nbase + j;
                    vpre[u] = (kj < NSEQ)
                        ? *(const float4*)&g_v[(((size_t)bh) * NSEQ + kj) * HDIM + 4 * vlcq]
                        : make_float4(0.f, 0.f, 0.f, 0.f);
                }
            }

            const int nquad = jmax >> 2;
            for (int qd = half; qd < nquad; qd += 2) {
                const int j0 = kbase + 4 * qd;
                const int jl = 4 * qd;
                float4 p4[4];
#pragma unroll
                for (int r = 0; r < 4; r++)
                    p4[r] = *(const float4*)&sc[(4 * qg + r) * SC_STRIDE + j0];
                const float* p0 = (const float*)&p4[0];
                const float* p1 = (const float*)&p4[1];
                const float* p2 = (const float*)&p4[2];
                const float* p3 = (const float*)&p4[3];
#pragma unroll
                for (int jj = 0; jj < 4; jj++) {
                    ulonglong2 vv = *(const ulonglong2*)&vs[(jl + jj) * VS_STRIDE + 4 * dg];
                    u64 w0, w1, w2, w3;
                    F32X2_DUP(w0, p0[jj]); F32X2_DUP(w1, p1[jj]);
                    F32X2_DUP(w2, p2[jj]); F32X2_DUP(w3, p3[jj]);
                    F32X2_FMA(oacc2[0][0], w0, vv.x, oacc2[0][0]);
                    F32X2_FMA(oacc2[0][1], w0, vv.y, oacc2[0][1]);
                    F32X2_FMA(oacc2[1][0], w1, vv.x, oacc2[1][0]);
                    F32X2_FMA(oacc2[1][1], w1, vv.y, oacc2[1][1]);
                    F32X2_FMA(oacc2[2][0], w2, vv.x, oacc2[2][0]);
                    F32X2_FMA(oacc2[2][1], w2, vv.y, oacc2[2][1]);
                    F32X2_FMA(oacc2[3][0], w3, vv.x, oacc2[3][0]);
                    F32X2_FMA(oacc2[3][1], w3, vv.y, oacc2[3][1]);
                }
            }
            __syncthreads();
        }

        float oacc[4][4];
#pragma unroll
        for (int r = 0; r < 4; r++) {
            F32X2_UNPACK(oacc[r][0], oacc[r][1], oacc2[r][0]);
            F32X2_UNPACK(oacc[r][2], oacc[r][3], oacc2[r][1]);
        }

        if (half == 1) {
#pragma unroll
            for (int r = 0; r < 4; r++)
                *(float4*)&red[ph * RED_STRIDE + 4 * r] =
                    make_float4(oacc[r][0], oacc[r][1], oacc[r][2], oacc[r][3]);
        }
        __syncthreads();
        if (half == 0) {
            const int b = bh / NHEAD, head = bh % NHEAD;
#pragma unroll
            for (int r = 0; r < 4; r++) {
                float4 o2 = *(const float4*)&red[ph * RED_STRIDE + 4 * r];
                int qi = q0 + 4 * qg + r;
                if (qi < NSEQ) {
                    float inv = sinv[4 * qg + r];
                    float4 ov = make_float4((oacc[r][0] + o2.x) * inv,
                                            (oacc[r][1] + o2.y) * inv,
                                            (oacc[r][2] + o2.z) * inv,
                                            (oacc[r][3] + o2.w) * inv);
                    *(float4*)&g_o[((size_t)(b * NSEQ + qi)) * CDIM + head * HDIM + 4 * dg] = ov;
                }
            }
        }
    }
}

// ---------------------------------------------------------------------------
// Kernel 4: proj GEMM. 128x128 tile, BK=16, 8x8 microtile, f32x2 packed FMA.
// ---------------------------------------------------------------------------
__global__ void __launch_bounds__(256) proj_gemm_kernel(
    const float* __restrict__ w, const float* __restrict__ bias,
    float* __restrict__ out)
{
    __shared__ float As[16 * AS_STRIDE];
    __shared__ float Bs[16 * 128];

    const int m0 = blockIdx.y * 128;
    const int n0 = blockIdx.x * 128;
    const int tid = threadIdx.x;
    const int tx = tid & 15, ty = tid >> 4;

    const int am = tid & 127;
    const int u0 = tid >> 7;
    int m_g = m0 + am; if (m_g > MTOT - 1) m_g = MTOT - 1;
    const float* aptr = g_o + (size_t)m_g * CDIM;

    const int kb = tid >> 5;
    const int nq = tid & 31;
    const float* bptr = w + n0 + 4 * nq;

    u64 acc2[8][4];
#pragma unroll
    for (int i = 0; i < 8; i++)
#pragma unroll
        for (int j = 0; j < 4; j++) acc2[i][j] = 0ULL;

    float4 av0 = *(const float4*)(aptr + 4 * u0);
    float4 av1 = *(const float4*)(aptr + 4 * u0 + 8);
    float4 bv0 = *(const float4*)(bptr + (size_t)kb * CDIM);
    float4 bv1 = *(const float4*)(bptr + (size_t)(kb + 8) * CDIM);

    for (int k0 = 0; k0 < CDIM; k0 += 16) {
        __syncthreads();
        As[(4 * u0 + 0) * AS_STRIDE + am] = av0.x;
        As[(4 * u0 + 1) * AS_STRIDE + am] = av0.y;
        As[(4 * u0 + 2) * AS_STRIDE + am] = av0.z;
        As[(4 * u0 + 3) * AS_STRIDE + am] = av0.w;
        As[(4 * u0 + 8) * AS_STRIDE + am] = av1.x;
        As[(4 * u0 + 9) * AS_STRIDE + am] = av1.y;
        As[(4 * u0 + 10) * AS_STRIDE + am] = av1.z;
        As[(4 * u0 + 11) * AS_STRIDE + am] = av1.w;
        *(float4*)&Bs[kb * 128 + 4 * nq] = bv0;
        *(float4*)&Bs[(kb + 8) * 128 + 4 * nq] = bv1;
        __syncthreads();

        {
            const int kn = (k0 + 16 < CDIM) ? (k0 + 16) : 0;
            av0 = *(const float4*)(aptr + kn + 4 * u0);
            av1 = *(const float4*)(aptr + kn + 4 * u0 + 8);
            bv0 = *(const float4*)(bptr + (size_t)(kn + kb) * CDIM);
            bv1 = *(const float4*)(bptr + (size_t)(kn + kb + 8) * CDIM);
        }

#pragma unroll
        for (int kk = 0; kk < 16; kk++) {
            float a[8];
            *(float4*)&a[0] = *(const float4*)&As[kk * AS_STRIDE + 8 * ty];
            *(float4*)&a[4] = *(const float4*)&As[kk * AS_STRIDE + 8 * ty + 4];
            ulonglong2 bl = *(const ulonglong2*)&Bs[kk * 128 + 8 * tx];
            ulonglong2 bh = *(const ulonglong2*)&Bs[kk * 128 + 8 * tx + 4];
#pragma unroll
            for (int i = 0; i < 8; i++) {
                u64 ad; F32X2_DUP(ad, a[i]);
                F32X2_FMA(acc2[i][0], ad, bl.x, acc2[i][0]);
                F32X2_FMA(acc2[i][1], ad, bl.y, acc2[i][1]);
                F32X2_FMA(acc2[i][2], ad, bh.x, acc2[i][2]);
                F32X2_FMA(acc2[i][3], ad, bh.y, acc2[i][3]);
            }
        }
    }

    float acc[8][8];
#pragma unroll
    for (int i = 0; i < 8; i++)
#pragma unroll
        for (int j = 0; j < 4; j++)
            F32X2_UNPACK(acc[i][2 * j], acc[i][2 * j + 1], acc2[i][j]);

    const size_t vp_base = (size_t)BATCH * 1024 * CDIM;   // 6291456
#pragma unroll
    for (int i = 0; i < 8; i++) {
        int m = m0 + 8 * ty + i;
        if (m >= MTOT) break;
        int b = m / NSEQ, n = m % NSEQ;
        size_t rowbase = (n < NTOK)
            ? vp_base + ((size_t)(b * NTOK + n)) * CDIM
            : ((size_t)(b * 1024 + (n - NTOK))) * CDIM;
#pragma unroll
        for (int jq = 0; jq < 2; jq++) {
            int col0 = n0 + 8 * tx + 4 * jq;
            float4 v4 = make_float4(acc[i][4 * jq + 0] + bias[col0 + 0],
                                    acc[i][4 * jq + 1] + bias[col0 + 1],
                                    acc[i][4 * jq + 2] + bias[col0 + 2],
                                    acc[i][4 * jq + 3] + bias[col0 + 3]);
            *(float4*)&out[rowbase + col0] = v4;
        }
    }
}

// ---------------------------------------------------------------------------
extern "C" void kernel_launch(void* const* d_in, const int* in_sizes, int n_in,
                              void* d_out, int out_size)
{
    const float* x      = (const float*)d_in[0];
    const float* vp     = (const float*)d_in[1];
    const float* qkv_w  = (const float*)d_in[2];
    const float* qkv_b  = (const float*)d_in[3];
    const float* proj_w = (const float*)d_in[4];
    const float* proj_b = (const float*)d_in[5];
    const float* rph    = (const float*)d_in[6];
    const float* rpw    = (const float*)d_in[7];
    float* out = (float*)d_out;

    cudaFuncSetAttribute(attn_kernel,
                         cudaFuncAttributeMaxDynamicSharedMemorySize,
                         ATTN_SMEM_BYTES);

    qkv_gemm_kernel<<<dim3(18, 65), 256>>>(x, vp, qkv_w, qkv_b);
    rel_kernel<<<dim3(32, 96), 256>>>(rph, rpw);
    attn_kernel<<<dim3(33, 96), 256, ATTN_SMEM_BYTES>>>();
    proj_gemm_kernel<<<dim3(6, 65), 256>>>(proj_w, proj_b, out);
}